// round 4
// baseline (speedup 1.0000x reference)
#include <cuda_runtime.h>
#include <cuda_fp16.h>
#include <math.h>
#include <stdint.h>

#define Bb   4
#define Ss   1024
#define Hh   16
#define Dd   64
#define HID  1024
#define BH   (Bb*Hh)
#define RR   181
#define RP   192

__device__ float  g_Q [(size_t)BH * Ss * Dd];
__device__ float  g_K [(size_t)BH * Ss * Dd];
__device__ float  g_V [(size_t)BH * Ss * Dd];
__device__ float  g_RS[(size_t)BH * Ss * RP];
__device__ float  g_BS[(size_t)BH * Ss * RP];
__device__ float  g_X [(size_t)Bb * Ss * HID];
__device__ float2 g_ML[(size_t)BH * Ss];

__device__ __forceinline__ uint32_t cvt_tf32(float x) {
    uint32_t r; asm("cvt.rna.tf32.f32 %0, %1;" : "=r"(r) : "f"(x)); return r;
}
__device__ __forceinline__ float cvtf_tf32(float x) { return __uint_as_float(cvt_tf32(x)); }
__device__ __forceinline__ void mma_tf32(float c[4], const uint32_t a[4], const uint32_t b[2]) {
    asm volatile(
        "mma.sync.aligned.m16n8k8.row.col.f32.tf32.tf32.f32 "
        "{%0,%1,%2,%3}, {%4,%5,%6,%7}, {%8,%9}, {%0,%1,%2,%3};"
        : "+f"(c[0]), "+f"(c[1]), "+f"(c[2]), "+f"(c[3])
        : "r"(a[0]), "r"(a[1]), "r"(a[2]), "r"(a[3]), "r"(b[0]), "r"(b[1]));
}
__device__ __forceinline__ void mma_f16(float c[4], const uint32_t a[4], const uint32_t b[2]) {
    asm volatile(
        "mma.sync.aligned.m16n8k16.row.col.f32.f16.f16.f32 "
        "{%0,%1,%2,%3}, {%4,%5,%6,%7}, {%8,%9}, {%0,%1,%2,%3};"
        : "+f"(c[0]), "+f"(c[1]), "+f"(c[2]), "+f"(c[3])
        : "r"(a[0]), "r"(a[1]), "r"(a[2]), "r"(a[3]), "r"(b[0]), "r"(b[1]));
}
__device__ __forceinline__ uint32_t pack_h2(float lo, float hi) {
    uint32_t r; asm("cvt.rn.f16x2.f32 %0, %1, %2;" : "=r"(r) : "f"(hi), "f"(lo)); return r;
}

// ================= tf32 GEMM: C = A @ W^T + bias =================
__global__ __launch_bounds__(256) void sgemm_bias_tc(
    const float* __restrict__ Ain, const float* __restrict__ W,
    const float* __restrict__ bias, float* __restrict__ Cout,
    int a_sel, int out_sel, int out_mode)
{
    const int K = HID, N = HID;
    __shared__ float As[32][136];
    __shared__ float Bs[32][136];
    const float* A = (a_sel == 1) ? g_X : Ain;
    float* C = (out_sel == 0) ? g_Q : (out_sel == 1) ? g_K : (out_sel == 2) ? g_V : Cout;
    const int tid = threadIdx.x, lane = tid & 31, wid = tid >> 5;
    const int gidq = lane >> 2, tig = lane & 3;
    const int warp_m = (wid & 1) * 64, warp_n = (wid >> 1) * 32;
    const int bm = blockIdx.y * 128, bn = blockIdx.x * 128;
    const int srow = tid & 31, scol = (tid >> 5) * 4;
    float acc[4][4][4];
    #pragma unroll
    for (int i = 0; i < 4; i++)
        #pragma unroll
        for (int j = 0; j < 4; j++)
            #pragma unroll
            for (int r = 0; r < 4; r++) acc[i][j][r] = 0.f;
    for (int k0 = 0; k0 < K; k0 += 32) {
        #pragma unroll
        for (int i = 0; i < 4; i++) {
            int ml = srow + 32 * i;
            float4 va = *(const float4*)(A + (size_t)(bm + ml) * K + k0 + scol);
            As[scol+0][ml]=cvtf_tf32(va.x); As[scol+1][ml]=cvtf_tf32(va.y);
            As[scol+2][ml]=cvtf_tf32(va.z); As[scol+3][ml]=cvtf_tf32(va.w);
            float4 vb = *(const float4*)(W + (size_t)(bn + ml) * K + k0 + scol);
            Bs[scol+0][ml]=cvtf_tf32(vb.x); Bs[scol+1][ml]=cvtf_tf32(vb.y);
            Bs[scol+2][ml]=cvtf_tf32(vb.z); Bs[scol+3][ml]=cvtf_tf32(vb.w);
        }
        __syncthreads();
        #pragma unroll
        for (int kk = 0; kk < 32; kk += 8) {
            uint32_t af[4][4], bf[4][2];
            #pragma unroll
            for (int ma = 0; ma < 4; ma++) {
                int m = warp_m + 16 * ma + gidq;
                af[ma][0]=__float_as_uint(As[kk+tig][m]);   af[ma][1]=__float_as_uint(As[kk+tig][m+8]);
                af[ma][2]=__float_as_uint(As[kk+tig+4][m]); af[ma][3]=__float_as_uint(As[kk+tig+4][m+8]);
            }
            #pragma unroll
            for (int nb = 0; nb < 4; nb++) {
                int n = warp_n + 8 * nb + gidq;
                bf[nb][0]=__float_as_uint(Bs[kk+tig][n]); bf[nb][1]=__float_as_uint(Bs[kk+tig+4][n]);
            }
            #pragma unroll
            for (int ma = 0; ma < 4; ma++)
                #pragma unroll
                for (int nb = 0; nb < 4; nb++)
                    mma_tf32(acc[ma][nb], af[ma], bf[nb]);
        }
        __syncthreads();
    }
    #pragma unroll
    for (int ma = 0; ma < 4; ma++) {
        int m0 = bm + warp_m + 16 * ma + gidq;
        #pragma unroll
        for (int nb = 0; nb < 4; nb++) {
            int n0 = bn + warp_n + 8 * nb + 2 * tig;
            float bx = bias[n0], by = bias[n0 + 1];
            #pragma unroll
            for (int half = 0; half < 2; half++) {
                int m = m0 + 8 * half;
                float vx = acc[ma][nb][2*half+0] + bx;
                float vy = acc[ma][nb][2*half+1] + by;
                if (out_mode == 0) {
                    *(float2*)(C + (size_t)m * N + n0) = make_float2(vx, vy);
                } else {
                    int b = m >> 10, s = m & 1023, h = n0 >> 6, d = n0 & 63;
                    *(float2*)(C + (((size_t)(b*Hh + h) * Ss) + s) * Dd + d) = make_float2(vx, vy);
                }
            }
        }
    }
}

// ================= RS = Q @ rel_k_emb^T =================
__global__ __launch_bounds__(256) void rel_scores_tc(const float* __restrict__ rk)
{
    __shared__ float As[32][136];
    __shared__ float Bs[32][200];
    int bh = blockIdx.y, q0 = blockIdx.x * 128;
    const int tid = threadIdx.x, lane = tid & 31, wid = tid >> 5;
    const int gidq = lane >> 2, tig = lane & 3;
    const int warp_m = (wid & 1) * 64, warp_n = (wid >> 1) * 48;
    const int srow = tid & 31, scol = (tid >> 5) * 4;
    const float* Qb = g_Q + ((size_t)bh * Ss + q0) * Dd;
    float acc[4][6][4];
    #pragma unroll
    for (int i = 0; i < 4; i++)
        #pragma unroll
        for (int j = 0; j < 6; j++)
            #pragma unroll
            for (int r = 0; r < 4; r++) acc[i][j][r] = 0.f;
    for (int k0 = 0; k0 < 64; k0 += 32) {
        #pragma unroll
        for (int i = 0; i < 4; i++) {
            int ml = srow + 32 * i;
            float4 va = *(const float4*)(Qb + (size_t)ml * Dd + k0 + scol);
            As[scol+0][ml]=cvtf_tf32(va.x); As[scol+1][ml]=cvtf_tf32(va.y);
            As[scol+2][ml]=cvtf_tf32(va.z); As[scol+3][ml]=cvtf_tf32(va.w);
        }
        #pragma unroll
        for (int i = 0; i < 6; i++) {
            int rl = srow + 32 * i;
            float4 vb = (rl < RR) ? *(const float4*)(rk + (size_t)rl * Dd + k0 + scol)
                                  : make_float4(0.f,0.f,0.f,0.f);
            Bs[scol+0][rl]=cvtf_tf32(vb.x); Bs[scol+1][rl]=cvtf_tf32(vb.y);
            Bs[scol+2][rl]=cvtf_tf32(vb.z); Bs[scol+3][rl]=cvtf_tf32(vb.w);
        }
        __syncthreads();
        #pragma unroll
        for (int kk = 0; kk < 32; kk += 8) {
            uint32_t af[4][4], bf[6][2];
            #pragma unroll
            for (int ma = 0; ma < 4; ma++) {
                int m = warp_m + 16 * ma + gidq;
                af[ma][0]=__float_as_uint(As[kk+tig][m]);   af[ma][1]=__float_as_uint(As[kk+tig][m+8]);
                af[ma][2]=__float_as_uint(As[kk+tig+4][m]); af[ma][3]=__float_as_uint(As[kk+tig+4][m+8]);
            }
            #pragma unroll
            for (int nb = 0; nb < 6; nb++) {
                int n = warp_n + 8 * nb + gidq;
                bf[nb][0]=__float_as_uint(Bs[kk+tig][n]); bf[nb][1]=__float_as_uint(Bs[kk+tig+4][n]);
            }
            #pragma unroll
            for (int ma = 0; ma < 4; ma++)
                #pragma unroll
                for (int nb = 0; nb < 6; nb++)
                    mma_tf32(acc[ma][nb], af[ma], bf[nb]);
        }
        __syncthreads();
    }
    float* out = g_RS + ((size_t)bh * Ss + q0) * RP;
    #pragma unroll
    for (int ma = 0; ma < 4; ma++) {
        int qm = warp_m + 16 * ma + gidq;
        #pragma unroll
        for (int nb = 0; nb < 6; nb++) {
            int r0 = warp_n + 8 * nb + 2 * tig;
            #pragma unroll
            for (int half = 0; half < 2; half++) {
                int q = qm + 8 * half;
                if (r0 < RR)     out[(size_t)q * RP + r0]     = acc[ma][nb][2*half+0];
                if (r0 + 1 < RR) out[(size_t)q * RP + r0 + 1] = acc[ma][nb][2*half+1];
            }
        }
    }
}

// ================= Fused flash attention =================
// 128 q rows/block, 8 warps (16 rows each), 8 k-tiles of 128.
// Writes: g_X = softmax(E)@V, g_BS band slots (raw energy), tails (final), g_ML.
__global__ __launch_bounds__(256) void flash_tc(
    const float* __restrict__ abse, const int* __restrict__ mask)
{
    extern __shared__ float smf[];
    float* Ks = smf;                          // [128][68] tf32-as-float
    __half* Vst = (__half*)(smf + 128*68);    // [64][136]  V^T (d,k)

    const int bh = blockIdx.y, q0 = blockIdx.x * 128;
    const int b = bh >> 4, h = bh & 15;
    const int tid = threadIdx.x, lane = tid & 31, wid = tid >> 5;
    const int gidq = lane >> 2, tig = lane & 3;
    const int r0 = q0 + wid * 16 + gidq, r1 = r0 + 8;
    const size_t bhSs = (size_t)bh * Ss;

    // Q fragments (register-resident): 8 k8-chunks
    uint32_t qf[8][4];
    {
        const float* Q0 = g_Q + (bhSs + r0) * Dd;
        const float* Q1 = g_Q + (bhSs + r1) * Dd;
        #pragma unroll
        for (int c = 0; c < 8; c++) {
            qf[c][0] = cvt_tf32(Q0[8*c + tig]);
            qf[c][1] = cvt_tf32(Q1[8*c + tig]);
            qf[c][2] = cvt_tf32(Q0[8*c + tig + 4]);
            qf[c][3] = cvt_tf32(Q1[8*c + tig + 4]);
        }
    }
    const float* RS0 = g_RS + (bhSs + r0) * RP;
    const float* RS1 = g_RS + (bhSs + r1) * RP;
    const float rs_lo0 = RS0[0], rs_hi0 = RS0[180];
    const float rs_lo1 = RS1[0], rs_hi1 = RS1[180];
    float* BS0 = g_BS + (bhSs + r0) * RP;
    float* BS1 = g_BS + (bhSs + r1) * RP;
    const float* ab0 = abse + ((size_t)h * Ss + r0) * Ss;
    const float* ab1 = abse + ((size_t)h * Ss + r1) * Ss;
    const int* mk0 = mask + ((size_t)b * Ss + r0) * Ss;
    const int* mk1 = mask + ((size_t)b * Ss + r1) * Ss;
    const float* Kg = g_K + bhSs * Dd;
    const float* Vg = g_V + bhSs * Dd;

    float m0 = -1e30f, m1 = -1e30f, l0 = 0.f, l1 = 0.f;
    float t00 = 0.f, t01 = 0.f, t10 = 0.f, t11 = 0.f;
    float accO[8][4];
    #pragma unroll
    for (int i = 0; i < 8; i++)
        #pragma unroll
        for (int j = 0; j < 4; j++) accO[i][j] = 0.f;

    for (int kt = 0; kt < 8; kt++) {
        const int k0 = kt * 128;
        __syncthreads();
        // K tile [k][d] as tf32
        for (int idx = tid; idx < 128 * 16; idx += 256) {
            int kr = idx >> 4, c4 = (idx & 15) * 4;
            float4 v = *(const float4*)(Kg + (size_t)(k0 + kr) * Dd + c4);
            Ks[kr*68 + c4+0] = cvtf_tf32(v.x); Ks[kr*68 + c4+1] = cvtf_tf32(v.y);
            Ks[kr*68 + c4+2] = cvtf_tf32(v.z); Ks[kr*68 + c4+3] = cvtf_tf32(v.w);
        }
        // V^T tile [d][k] as fp16
        for (int idx = tid; idx < 128 * 32; idx += 256) {
            int kr = idx >> 5, dp = idx & 31;
            float2 v = *(const float2*)(Vg + (size_t)(k0 + kr) * Dd + 2*dp);
            Vst[(2*dp)   * 136 + kr] = __float2half(v.x);
            Vst[(2*dp+1) * 136 + kr] = __float2half(v.y);
        }
        __syncthreads();

        // S = Q K^T (16 x 128 per warp)
        float accS[16][4];
        #pragma unroll
        for (int nb = 0; nb < 16; nb++)
            #pragma unroll
            for (int r = 0; r < 4; r++) accS[nb][r] = 0.f;
        #pragma unroll
        for (int c = 0; c < 8; c++) {
            #pragma unroll
            for (int nb = 0; nb < 16; nb++) {
                uint32_t bf[2];
                int n = nb * 8 + gidq;
                bf[0] = __float_as_uint(Ks[n*68 + 8*c + tig]);
                bf[1] = __float_as_uint(Ks[n*68 + 8*c + tig + 4]);
                mma_tf32(accS[nb], qf[c], bf);
            }
        }
        // energy epilogue + band stores
        float mt0 = -1e30f, mt1 = -1e30f;
        #pragma unroll
        for (int nb = 0; nb < 16; nb++) {
            int kc = k0 + nb * 8 + 2 * tig;
            float2 av = *(const float2*)(ab0 + kc);
            int2 mv = *(const int2*)(mk0 + kc);
            int d0 = kc - r0;
            float rv0 = (d0 <= -90) ? rs_lo0 : (d0 >= 90) ? rs_hi0 : RS0[d0 + 90];
            float rv1 = (d0+1 <= -90) ? rs_lo0 : (d0+1 >= 90) ? rs_hi0 : RS0[d0 + 91];
            float e0 = (accS[nb][0] + av.x + rv0) * 0.125f; if (!mv.x) e0 = -1e10f;
            float e1 = (accS[nb][1] + av.y + rv1) * 0.125f; if (!mv.y) e1 = -1e10f;
            if (d0 > -90 && d0 < 90)     BS0[d0 + 90] = e0;
            if (d0+1 > -90 && d0+1 < 90) BS0[d0 + 91] = e1;
            accS[nb][0] = e0; accS[nb][1] = e1;
            mt0 = fmaxf(mt0, fmaxf(e0, e1));
            float2 aw = *(const float2*)(ab1 + kc);
            int2 mw = *(const int2*)(mk1 + kc);
            int d2 = kc - r1;
            float rv2 = (d2 <= -90) ? rs_lo1 : (d2 >= 90) ? rs_hi1 : RS1[d2 + 90];
            float rv3 = (d2+1 <= -90) ? rs_lo1 : (d2+1 >= 90) ? rs_hi1 : RS1[d2 + 91];
            float e2 = (accS[nb][2] + aw.x + rv2) * 0.125f; if (!mw.x) e2 = -1e10f;
            float e3 = (accS[nb][3] + aw.y + rv3) * 0.125f; if (!mw.y) e3 = -1e10f;
            if (d2 > -90 && d2 < 90)     BS1[d2 + 90] = e2;
            if (d2+1 > -90 && d2+1 < 90) BS1[d2 + 91] = e3;
            accS[nb][2] = e2; accS[nb][3] = e3;
            mt1 = fmaxf(mt1, fmaxf(e2, e3));
        }
        mt0 = fmaxf(mt0, __shfl_xor_sync(0xffffffffu, mt0, 1));
        mt0 = fmaxf(mt0, __shfl_xor_sync(0xffffffffu, mt0, 2));
        mt1 = fmaxf(mt1, __shfl_xor_sync(0xffffffffu, mt1, 1));
        mt1 = fmaxf(mt1, __shfl_xor_sync(0xffffffffu, mt1, 2));
        float mn0 = fmaxf(m0, mt0), mn1 = fmaxf(m1, mt1);
        float sc0 = __expf(m0 - mn0), sc1 = __expf(m1 - mn1);
        m0 = mn0; m1 = mn1;
        l0 *= sc0; l1 *= sc1; t00 *= sc0; t01 *= sc0; t10 *= sc1; t11 *= sc1;
        #pragma unroll
        for (int nd = 0; nd < 8; nd++) {
            accO[nd][0] *= sc0; accO[nd][1] *= sc0;
            accO[nd][2] *= sc1; accO[nd][3] *= sc1;
        }
        // exp + tails
        #pragma unroll
        for (int nb = 0; nb < 16; nb++) {
            int kc = k0 + nb * 8 + 2 * tig;
            float p0 = __expf(accS[nb][0] - m0);
            float p1 = __expf(accS[nb][1] - m0);
            float p2 = __expf(accS[nb][2] - m1);
            float p3 = __expf(accS[nb][3] - m1);
            accS[nb][0] = p0; accS[nb][1] = p1; accS[nb][2] = p2; accS[nb][3] = p3;
            l0 += p0 + p1; l1 += p2 + p3;
            int d0 = kc - r0, d2 = kc - r1;
            if (d0 <= -90) t00 += p0; else if (d0 >= 90) t01 += p0;
            if (d0+1 <= -90) t00 += p1; else if (d0+1 >= 90) t01 += p1;
            if (d2 <= -90) t10 += p2; else if (d2 >= 90) t11 += p2;
            if (d2+1 <= -90) t10 += p3; else if (d2+1 >= 90) t11 += p3;
        }
        // PV (fp16): 8 k16-chunks
        #pragma unroll
        for (int j = 0; j < 8; j++) {
            uint32_t aP[4];
            aP[0] = pack_h2(accS[2*j][0],   accS[2*j][1]);
            aP[1] = pack_h2(accS[2*j][2],   accS[2*j][3]);
            aP[2] = pack_h2(accS[2*j+1][0], accS[2*j+1][1]);
            aP[3] = pack_h2(accS[2*j+1][2], accS[2*j+1][3]);
            #pragma unroll
            for (int nd = 0; nd < 8; nd++) {
                int n = nd * 8 + gidq;
                uint32_t bV[2];
                bV[0] = *(const uint32_t*)&Vst[n*136 + 16*j + 2*tig];
                bV[1] = *(const uint32_t*)&Vst[n*136 + 16*j + 2*tig + 8];
                mma_f16(accO[nd], aP, bV);
            }
        }
    }
    // quad reductions
    #pragma unroll
    for (int o = 1; o <= 2; o <<= 1) {
        l0 += __shfl_xor_sync(0xffffffffu, l0, o);
        l1 += __shfl_xor_sync(0xffffffffu, l1, o);
        t00 += __shfl_xor_sync(0xffffffffu, t00, o);
        t01 += __shfl_xor_sync(0xffffffffu, t01, o);
        t10 += __shfl_xor_sync(0xffffffffu, t10, o);
        t11 += __shfl_xor_sync(0xffffffffu, t11, o);
    }
    float inv0 = 1.f / l0, inv1 = 1.f / l1;
    if (tig == 0) {
        g_ML[bhSs + r0] = make_float2(m0, inv0);
        g_ML[bhSs + r1] = make_float2(m1, inv1);
        BS0[0] = t00 * inv0; BS0[180] = t01 * inv0;
        BS1[0] = t10 * inv1; BS1[180] = t11 * inv1;
    }
    float* X0 = g_X + ((size_t)(b*Ss + r0)) * HID + h * Dd;
    float* X1 = g_X + ((size_t)(b*Ss + r1)) * HID + h * Dd;
    #pragma unroll
    for (int nd = 0; nd < 8; nd++) {
        int d = nd * 8 + 2 * tig;
        *(float2*)(X0 + d) = make_float2(accO[nd][0] * inv0, accO[nd][1] * inv0);
        *(float2*)(X1 + d) = make_float2(accO[nd][2] * inv1, accO[nd][3] * inv1);
    }
}

// ================= BS band normalize =================
__global__ __launch_bounds__(192) void bs_finalize()
{
    int q = blockIdx.x, bh = blockIdx.y, r = threadIdx.x;
    float* out = g_BS + ((size_t)bh * Ss + q) * RP;
    if (r >= 1 && r <= 179) {
        int k = q + r - 90;
        if (k < 0 || k >= Ss) out[r] = 0.f;
        else {
            float2 ml = g_ML[(size_t)bh * Ss + q];
            out[r] = __expf(out[r] - ml.x) * ml.y;
        }
    }
}

// ================= g_X += BS @ rel_v_emb =================
__global__ __launch_bounds__(256) void rx_add_kernel(const float* __restrict__ rv)
{
    extern __shared__ float sm[];
    float (*BSs)[193] = (float(*)[193])sm;
    float (*rvs)[64]  = (float(*)[64])(sm + 64*193);
    int bh = blockIdx.y, q0 = blockIdx.x * 64;
    int tid = threadIdx.x, tx = tid & 15, ty = tid >> 4;
    const float* BSb = g_BS + ((size_t)bh * Ss + q0) * RP;
    for (int idx = tid; idx < 64*RP; idx += 256) {
        int q = idx / RP, r = idx % RP;
        BSs[q][r] = BSb[idx];
    }
    for (int idx = tid; idx < RR*64; idx += 256) {
        int r = idx >> 6, d = idx & 63;
        rvs[r][d] = rv[idx];
    }
    __syncthreads();
    float acc[4][4];
    #pragma unroll
    for (int i = 0; i < 4; i++)
        #pragma unroll
        for (int j = 0; j < 4; j++) acc[i][j] = 0.f;
    for (int r = 0; r < RR; r++) {
        float af[4], bf[4];
        #pragma unroll
        for (int i = 0; i < 4; i++) af[i] = BSs[ty + 16*i][r];
        #pragma unroll
        for (int j = 0; j < 4; j++) bf[j] = rvs[r][tx + 16*j];
        #pragma unroll
        for (int i = 0; i < 4; i++)
            #pragma unroll
            for (int j = 0; j < 4; j++)
                acc[i][j] += af[i] * bf[j];
    }
    int b = bh >> 4, h = bh & 15;
    #pragma unroll
    for (int i = 0; i < 4; i++) {
        int q = q0 + ty + 16*i;
        #pragma unroll
        for (int j = 0; j < 4; j++) {
            int d = tx + 16*j;
            g_X[((size_t)(b*Ss + q)) * HID + h*Dd + d] += acc[i][j];
        }
    }
}

extern "C" void kernel_launch(void* const* d_in, const int* in_sizes, int n_in,
                              void* d_out, int out_size)
{
    const float* query = (const float*)d_in[0];
    const float* key   = (const float*)d_in[1];
    const float* value = (const float*)d_in[2];
    const int*   mask  = (const int*)  d_in[3];
    const float* abse  = (const float*)d_in[4];
    const float* Wq    = (const float*)d_in[5];
    const float* bq    = (const float*)d_in[6];
    const float* Wk    = (const float*)d_in[7];
    const float* bk    = (const float*)d_in[8];
    const float* Wv    = (const float*)d_in[9];
    const float* bv    = (const float*)d_in[10];
    const float* Wo    = (const float*)d_in[11];
    const float* bo    = (const float*)d_in[12];
    const float* rk    = (const float*)d_in[13];
    const float* rv    = (const float*)d_in[14];
    float* out = (float*)d_out;

    const int smem_rx = (64*193 + RR*64) * 4;
    const int smem_fl = 128*68*4 + 64*136*2;
    cudaFuncSetAttribute(rx_add_kernel, cudaFuncAttributeMaxDynamicSharedMemorySize, smem_rx);
    cudaFuncSetAttribute(flash_tc, cudaFuncAttributeMaxDynamicSharedMemorySize, smem_fl);

    dim3 gProj(HID/128, (Bb*Ss)/128);
    sgemm_bias_tc<<<gProj, 256>>>(query, Wq, bq, nullptr, 0, 0, 1);
    sgemm_bias_tc<<<gProj, 256>>>(key,   Wk, bk, nullptr, 0, 1, 1);
    sgemm_bias_tc<<<gProj, 256>>>(value, Wv, bv, nullptr, 0, 2, 1);

    rel_scores_tc<<<dim3(Ss/128, BH), 256>>>(rk);
    flash_tc<<<dim3(Ss/128, BH), 256, smem_fl>>>(abse, mask);
    bs_finalize<<<dim3(Ss, BH), 192>>>();
    rx_add_kernel<<<dim3(Ss/64, BH), 256, smem_rx>>>(rv);

    sgemm_bias_tc<<<gProj, 256>>>(nullptr, Wo, bo, out, 1, -1, 0);
}

// round 5
// speedup vs baseline: 1.5074x; 1.5074x over previous
#include <cuda_runtime.h>
#include <cuda_fp16.h>
#include <math.h>
#include <stdint.h>

#define Bb   4
#define Ss   1024
#define Hh   16
#define Dd   64
#define HID  1024
#define BH   (Bb*Hh)
#define RR   181
#define RP   192
#define TK   64

__device__ float  g_Q [(size_t)BH * Ss * Dd];
__device__ __half g_Kh[(size_t)BH * Ss * Dd];   // [bh][s][d]
__device__ __half g_Vh[(size_t)BH * Dd * Ss];   // [bh][d][s] (transposed)
__device__ float  g_RS[(size_t)BH * Ss * RP];
__device__ float  g_BS[(size_t)BH * Ss * RP];
__device__ float  g_X [(size_t)Bb * Ss * HID];
__device__ float2 g_ML[(size_t)BH * Ss];

__device__ __forceinline__ uint32_t cvt_tf32(float x) {
    uint32_t r; asm("cvt.rna.tf32.f32 %0, %1;" : "=r"(r) : "f"(x)); return r;
}
__device__ __forceinline__ void mma_tf32(float c[4], const uint32_t a[4], const uint32_t b[2]) {
    asm volatile(
        "mma.sync.aligned.m16n8k8.row.col.f32.tf32.tf32.f32 "
        "{%0,%1,%2,%3}, {%4,%5,%6,%7}, {%8,%9}, {%0,%1,%2,%3};"
        : "+f"(c[0]), "+f"(c[1]), "+f"(c[2]), "+f"(c[3])
        : "r"(a[0]), "r"(a[1]), "r"(a[2]), "r"(a[3]), "r"(b[0]), "r"(b[1]));
}
__device__ __forceinline__ void mma_f16(float c[4], const uint32_t a[4], const uint32_t b[2]) {
    asm volatile(
        "mma.sync.aligned.m16n8k16.row.col.f32.f16.f16.f32 "
        "{%0,%1,%2,%3}, {%4,%5,%6,%7}, {%8,%9}, {%0,%1,%2,%3};"
        : "+f"(c[0]), "+f"(c[1]), "+f"(c[2]), "+f"(c[3])
        : "r"(a[0]), "r"(a[1]), "r"(a[2]), "r"(a[3]), "r"(b[0]), "r"(b[1]));
}
__device__ __forceinline__ uint32_t pack_h2(float lo, float hi) {
    uint32_t r; asm("cvt.rn.f16x2.f32 %0, %1, %2;" : "=r"(r) : "f"(hi), "f"(lo)); return r;
}
__device__ __forceinline__ void cpa16(void* s, const void* g) {
    uint32_t sa = (uint32_t)__cvta_generic_to_shared(s);
    asm volatile("cp.async.cg.shared.global [%0], [%1], 16;" :: "r"(sa), "l"(g));
}
__device__ __forceinline__ void cp_commit() { asm volatile("cp.async.commit_group;"); }
__device__ __forceinline__ void cp_wait1()  { asm volatile("cp.async.wait_group 1;"); }

// ================= tf32 GEMM, cp.async 2-stage: C = A @ W^T + bias =================
// out_mode: 0 Cout f32 [M,N]; 1 g_Q f32 [bh][s][d]; 2 g_Kh half [bh][s][d]; 3 g_Vh half [bh][d][s]
__device__ __forceinline__ void gemm_load(float* As, float* Bs,
    const float* A, const float* W, int bm, int bn, int k0, int tid)
{
    #pragma unroll
    for (int i = 0; i < 4; i++) {
        int idx = tid + 256 * i;
        int row = idx >> 3, c = (idx & 7) * 4;
        cpa16(&As[row*36 + c], A + (size_t)(bm + row) * HID + k0 + c);
        cpa16(&Bs[row*36 + c], W + (size_t)(bn + row) * HID + k0 + c);
    }
}

__global__ __launch_bounds__(256) void sgemm_bias_tc(
    const float* __restrict__ Ain, const float* __restrict__ W,
    const float* __restrict__ bias, float* __restrict__ Cout,
    int a_sel, int out_mode)
{
    extern __shared__ float smg[];
    float* As[2] = { smg, smg + 128*36 };
    float* Bs[2] = { smg + 2*128*36, smg + 3*128*36 };
    const float* A = (a_sel == 1) ? g_X : Ain;
    const int tid = threadIdx.x, lane = tid & 31, wid = tid >> 5;
    const int gidq = lane >> 2, tig = lane & 3;
    const int warp_m = (wid & 1) * 64, warp_n = (wid >> 1) * 32;
    const int bm = blockIdx.y * 128, bn = blockIdx.x * 128;

    float acc[4][4][4];
    #pragma unroll
    for (int i = 0; i < 4; i++)
        #pragma unroll
        for (int j = 0; j < 4; j++)
            #pragma unroll
            for (int r = 0; r < 4; r++) acc[i][j][r] = 0.f;

    gemm_load(As[0], Bs[0], A, W, bm, bn, 0, tid);
    cp_commit();

    for (int it = 0; it < 32; it++) {
        int st = it & 1;
        if (it < 31) gemm_load(As[st^1], Bs[st^1], A, W, bm, bn, (it+1)*32, tid);
        cp_commit();
        cp_wait1();
        __syncthreads();
        const float* Ap = As[st];
        const float* Bp = Bs[st];
        #pragma unroll
        for (int kk = 0; kk < 32; kk += 8) {
            uint32_t af[4][4], bf[4][2];
            #pragma unroll
            for (int ma = 0; ma < 4; ma++) {
                int m = warp_m + 16 * ma + gidq;
                af[ma][0] = cvt_tf32(Ap[m*36 + kk + tig]);
                af[ma][1] = cvt_tf32(Ap[(m+8)*36 + kk + tig]);
                af[ma][2] = cvt_tf32(Ap[m*36 + kk + tig + 4]);
                af[ma][3] = cvt_tf32(Ap[(m+8)*36 + kk + tig + 4]);
            }
            #pragma unroll
            for (int nb = 0; nb < 4; nb++) {
                int n = warp_n + 8 * nb + gidq;
                bf[nb][0] = cvt_tf32(Bp[n*36 + kk + tig]);
                bf[nb][1] = cvt_tf32(Bp[n*36 + kk + tig + 4]);
            }
            #pragma unroll
            for (int ma = 0; ma < 4; ma++)
                #pragma unroll
                for (int nb = 0; nb < 4; nb++)
                    mma_tf32(acc[ma][nb], af[ma], bf[nb]);
        }
        __syncthreads();
    }

    #pragma unroll
    for (int ma = 0; ma < 4; ma++) {
        #pragma unroll
        for (int nb = 0; nb < 4; nb++) {
            int n0 = bn + warp_n + 8 * nb + 2 * tig;
            float bx = bias[n0], by = bias[n0 + 1];
            #pragma unroll
            for (int half = 0; half < 2; half++) {
                int m = bm + warp_m + 16 * ma + gidq + 8 * half;
                float vx = acc[ma][nb][2*half+0] + bx;
                float vy = acc[ma][nb][2*half+1] + by;
                if (out_mode == 0) {
                    *(float2*)(Cout + (size_t)m * HID + n0) = make_float2(vx, vy);
                } else {
                    int b = m >> 10, s = m & 1023, h = n0 >> 6, d = n0 & 63;
                    size_t bh = (size_t)(b * Hh + h);
                    if (out_mode == 1) {
                        *(float2*)(g_Q + (bh * Ss + s) * Dd + d) = make_float2(vx, vy);
                    } else if (out_mode == 2) {
                        *(__half2*)(g_Kh + (bh * Ss + s) * Dd + d) = __floats2half2_rn(vx, vy);
                    } else {
                        g_Vh[(bh * Dd + d) * Ss + s]     = __float2half(vx);
                        g_Vh[(bh * Dd + d + 1) * Ss + s] = __float2half(vy);
                    }
                }
            }
        }
    }
}

// ================= RS = Q @ rel_k_emb^T (tf32) =================
__global__ __launch_bounds__(256) void rel_scores_tc(const float* __restrict__ rk)
{
    __shared__ float As[32][136];
    __shared__ float Bs[32][200];
    int bh = blockIdx.y, q0 = blockIdx.x * 128;
    const int tid = threadIdx.x, lane = tid & 31, wid = tid >> 5;
    const int gidq = lane >> 2, tig = lane & 3;
    const int warp_m = (wid & 1) * 64, warp_n = (wid >> 1) * 48;
    const int srow = tid & 31, scol = (tid >> 5) * 4;
    const float* Qb = g_Q + ((size_t)bh * Ss + q0) * Dd;
    float acc[4][6][4];
    #pragma unroll
    for (int i = 0; i < 4; i++)
        #pragma unroll
        for (int j = 0; j < 6; j++)
            #pragma unroll
            for (int r = 0; r < 4; r++) acc[i][j][r] = 0.f;
    for (int k0 = 0; k0 < 64; k0 += 32) {
        #pragma unroll
        for (int i = 0; i < 4; i++) {
            int ml = srow + 32 * i;
            float4 va = *(const float4*)(Qb + (size_t)ml * Dd + k0 + scol);
            As[scol+0][ml]=__uint_as_float(cvt_tf32(va.x)); As[scol+1][ml]=__uint_as_float(cvt_tf32(va.y));
            As[scol+2][ml]=__uint_as_float(cvt_tf32(va.z)); As[scol+3][ml]=__uint_as_float(cvt_tf32(va.w));
        }
        #pragma unroll
        for (int i = 0; i < 6; i++) {
            int rl = srow + 32 * i;
            float4 vb = (rl < RR) ? *(const float4*)(rk + (size_t)rl * Dd + k0 + scol)
                                  : make_float4(0.f,0.f,0.f,0.f);
            Bs[scol+0][rl]=__uint_as_float(cvt_tf32(vb.x)); Bs[scol+1][rl]=__uint_as_float(cvt_tf32(vb.y));
            Bs[scol+2][rl]=__uint_as_float(cvt_tf32(vb.z)); Bs[scol+3][rl]=__uint_as_float(cvt_tf32(vb.w));
        }
        __syncthreads();
        #pragma unroll
        for (int kk = 0; kk < 32; kk += 8) {
            uint32_t af[4][4], bf[6][2];
            #pragma unroll
            for (int ma = 0; ma < 4; ma++) {
                int m = warp_m + 16 * ma + gidq;
                af[ma][0]=__float_as_uint(As[kk+tig][m]);   af[ma][1]=__float_as_uint(As[kk+tig][m+8]);
                af[ma][2]=__float_as_uint(As[kk+tig+4][m]); af[ma][3]=__float_as_uint(As[kk+tig+4][m+8]);
            }
            #pragma unroll
            for (int nb = 0; nb < 6; nb++) {
                int n = warp_n + 8 * nb + gidq;
                bf[nb][0]=__float_as_uint(Bs[kk+tig][n]); bf[nb][1]=__float_as_uint(Bs[kk+tig+4][n]);
            }
            #pragma unroll
            for (int ma = 0; ma < 4; ma++)
                #pragma unroll
                for (int nb = 0; nb < 6; nb++)
                    mma_tf32(acc[ma][nb], af[ma], bf[nb]);
        }
        __syncthreads();
    }
    float* out = g_RS + ((size_t)bh * Ss + q0) * RP;
    #pragma unroll
    for (int ma = 0; ma < 4; ma++) {
        int qm = warp_m + 16 * ma + gidq;
        #pragma unroll
        for (int nb = 0; nb < 6; nb++) {
            int r0 = warp_n + 8 * nb + 2 * tig;
            #pragma unroll
            for (int half = 0; half < 2; half++) {
                int q = qm + 8 * half;
                if (r0 < RR)     out[(size_t)q * RP + r0]     = acc[ma][nb][2*half+0];
                if (r0 + 1 < RR) out[(size_t)q * RP + r0 + 1] = acc[ma][nb][2*half+1];
            }
        }
    }
}

// ================= Fused flash attention (fp16 mma, cp.async 2-stage) =================
// stage layout (bytes): Kt half[64][72] @0 (9216) | Vt half[64][136] @9216 (17408)
//                       ab float[128][68] @26624 (34816) | mk int[128][68] @61440 (34816)
#define FL_ST 96256

__device__ __forceinline__ void flash_load_tile(char* base, int kt, int tid,
    const __half* Kg, const __half* Vg, const float* abrow, const int* mkrow)
{
    __half* Ktp = (__half*)base;
    __half* Vtp = (__half*)(base + 9216);
    float*  abp = (float*)(base + 26624);
    int*    mkp = (int*)(base + 61440);
    int k0 = kt * TK;
    #pragma unroll
    for (int i = 0; i < 2; i++) {
        int idx = tid + 256 * i;
        int r = idx >> 3, c = (idx & 7) * 8;
        cpa16(&Ktp[r*72 + c], Kg + (size_t)(k0 + r) * Dd + c);
        cpa16(&Vtp[r*136 + c], Vg + (size_t)r * Ss + k0 + c);
    }
    #pragma unroll
    for (int i = 0; i < 8; i++) {
        int idx = tid + 256 * i;
        int r = idx >> 4, c = (idx & 15) * 4;
        cpa16(&abp[r*68 + c], abrow + (size_t)r * Ss + k0 + c);
        cpa16(&mkp[r*68 + c], mkrow + (size_t)r * Ss + k0 + c);
    }
}

__global__ __launch_bounds__(256) void flash_tc(
    const float* __restrict__ abse, const int* __restrict__ mask)
{
    extern __shared__ char smb[];
    const int bh = blockIdx.y, q0 = blockIdx.x * 128;
    const int b = bh >> 4, h = bh & 15;
    const int tid = threadIdx.x, lane = tid & 31, wid = tid >> 5;
    const int gidq = lane >> 2, tig = lane & 3;
    const int ql0 = wid * 16 + gidq, ql1 = ql0 + 8;
    const int r0 = q0 + ql0, r1 = q0 + ql1;
    const size_t bhSs = (size_t)bh * Ss;
    const __half* Kg = g_Kh + bhSs * Dd;
    const __half* Vg = g_Vh + (size_t)bh * Dd * Ss;
    const float* abrow = abse + ((size_t)h * Ss + q0) * Ss;
    const int*   mkrow = mask + ((size_t)b * Ss + q0) * Ss;

    // Q fragments (fp16 pairs along d)
    uint32_t qh[4][4];
    {
        const float* Q0 = g_Q + (bhSs + r0) * Dd;
        const float* Q1 = g_Q + (bhSs + r1) * Dd;
        #pragma unroll
        for (int c = 0; c < 4; c++) {
            float2 a0 = *(const float2*)(Q0 + 16*c + 2*tig);
            float2 a1 = *(const float2*)(Q1 + 16*c + 2*tig);
            float2 a2 = *(const float2*)(Q0 + 16*c + 2*tig + 8);
            float2 a3 = *(const float2*)(Q1 + 16*c + 2*tig + 8);
            qh[c][0] = pack_h2(a0.x, a0.y); qh[c][1] = pack_h2(a1.x, a1.y);
            qh[c][2] = pack_h2(a2.x, a2.y); qh[c][3] = pack_h2(a3.x, a3.y);
        }
    }
    const float* RS0 = g_RS + (bhSs + r0) * RP;
    const float* RS1 = g_RS + (bhSs + r1) * RP;
    const float rs_lo0 = RS0[0], rs_hi0 = RS0[180];
    const float rs_lo1 = RS1[0], rs_hi1 = RS1[180];
    float* BS0 = g_BS + (bhSs + r0) * RP;
    float* BS1 = g_BS + (bhSs + r1) * RP;

    flash_load_tile(smb, 0, tid, Kg, Vg, abrow, mkrow);
    cp_commit();

    float m0 = -1e30f, m1 = -1e30f, l0 = 0.f, l1 = 0.f;
    float t00 = 0.f, t01 = 0.f, t10 = 0.f, t11 = 0.f;
    float accO[8][4];
    #pragma unroll
    for (int i = 0; i < 8; i++)
        #pragma unroll
        for (int j = 0; j < 4; j++) accO[i][j] = 0.f;

    for (int kt = 0; kt < 16; kt++) {
        const int st = kt & 1;
        if (kt < 15) flash_load_tile(smb + (st^1)*FL_ST, kt+1, tid, Kg, Vg, abrow, mkrow);
        cp_commit();
        cp_wait1();
        __syncthreads();
        char* base = smb + st * FL_ST;
        const __half* Ktp = (const __half*)base;
        const __half* Vtp = (const __half*)(base + 9216);
        const float*  abp = (const float*)(base + 26624);
        const int*    mkp = (const int*)(base + 61440);
        const int k0 = kt * TK;

        // S = Q K^T  (16 x 64 per warp)
        float accS[8][4];
        #pragma unroll
        for (int nb = 0; nb < 8; nb++)
            #pragma unroll
            for (int r = 0; r < 4; r++) accS[nb][r] = 0.f;
        #pragma unroll
        for (int c = 0; c < 4; c++) {
            #pragma unroll
            for (int nb = 0; nb < 8; nb++) {
                int n = nb * 8 + gidq;
                uint32_t bf[2];
                bf[0] = *(const uint32_t*)&Ktp[n*72 + 16*c + 2*tig];
                bf[1] = *(const uint32_t*)&Ktp[n*72 + 16*c + 2*tig + 8];
                mma_f16(accS[nb], qh[c], bf);
            }
        }
        // energy epilogue + band stores
        float mt0 = -1e30f, mt1 = -1e30f;
        #pragma unroll
        for (int nb = 0; nb < 8; nb++) {
            int kcl = nb * 8 + 2 * tig;
            int kc = k0 + kcl;
            float2 av = *(const float2*)&abp[ql0*68 + kcl];
            int2   mv = *(const int2*)&mkp[ql0*68 + kcl];
            int d0 = kc - r0;
            float rv0 = (d0 <= -90) ? rs_lo0 : (d0 >= 90) ? rs_hi0 : RS0[d0 + 90];
            float rv1 = (d0+1 <= -90) ? rs_lo0 : (d0+1 >= 90) ? rs_hi0 : RS0[d0 + 91];
            float e0 = (accS[nb][0] + av.x + rv0) * 0.125f; if (!mv.x) e0 = -1e10f;
            float e1 = (accS[nb][1] + av.y + rv1) * 0.125f; if (!mv.y) e1 = -1e10f;
            if (d0 > -90 && d0 < 90)     BS0[d0 + 90] = e0;
            if (d0+1 > -90 && d0+1 < 90) BS0[d0 + 91] = e1;
            accS[nb][0] = e0; accS[nb][1] = e1;
            mt0 = fmaxf(mt0, fmaxf(e0, e1));
            float2 aw = *(const float2*)&abp[ql1*68 + kcl];
            int2   mw = *(const int2*)&mkp[ql1*68 + kcl];
            int d2 = kc - r1;
            float rv2 = (d2 <= -90) ? rs_lo1 : (d2 >= 90) ? rs_hi1 : RS1[d2 + 90];
            float rv3 = (d2+1 <= -90) ? rs_lo1 : (d2+1 >= 90) ? rs_hi1 : RS1[d2 + 91];
            float e2 = (accS[nb][2] + aw.x + rv2) * 0.125f; if (!mw.x) e2 = -1e10f;
            float e3 = (accS[nb][3] + aw.y + rv3) * 0.125f; if (!mw.y) e3 = -1e10f;
            if (d2 > -90 && d2 < 90)     BS1[d2 + 90] = e2;
            if (d2+1 > -90 && d2+1 < 90) BS1[d2 + 91] = e3;
            accS[nb][2] = e2; accS[nb][3] = e3;
            mt1 = fmaxf(mt1, fmaxf(e2, e3));
        }
        mt0 = fmaxf(mt0, __shfl_xor_sync(0xffffffffu, mt0, 1));
        mt0 = fmaxf(mt0, __shfl_xor_sync(0xffffffffu, mt0, 2));
        mt1 = fmaxf(mt1, __shfl_xor_sync(0xffffffffu, mt1, 1));
        mt1 = fmaxf(mt1, __shfl_xor_sync(0xffffffffu, mt1, 2));
        float mn0 = fmaxf(m0, mt0), mn1 = fmaxf(m1, mt1);
        float sc0 = __expf(m0 - mn0), sc1 = __expf(m1 - mn1);
        m0 = mn0; m1 = mn1;
        l0 *= sc0; l1 *= sc1; t00 *= sc0; t01 *= sc0; t10 *= sc1; t11 *= sc1;
        #pragma unroll
        for (int nd = 0; nd < 8; nd++) {
            accO[nd][0] *= sc0; accO[nd][1] *= sc0;
            accO[nd][2] *= sc1; accO[nd][3] *= sc1;
        }
        #pragma unroll
        for (int nb = 0; nb < 8; nb++) {
            int kc = k0 + nb * 8 + 2 * tig;
            float p0 = __expf(accS[nb][0] - m0);
            float p1 = __expf(accS[nb][1] - m0);
            float p2 = __expf(accS[nb][2] - m1);
            float p3 = __expf(accS[nb][3] - m1);
            accS[nb][0] = p0; accS[nb][1] = p1; accS[nb][2] = p2; accS[nb][3] = p3;
            l0 += p0 + p1; l1 += p2 + p3;
            int d0 = kc - r0, d2 = kc - r1;
            if (d0 <= -90) t00 += p0; else if (d0 >= 90) t01 += p0;
            if (d0+1 <= -90) t00 += p1; else if (d0+1 >= 90) t01 += p1;
            if (d2 <= -90) t10 += p2; else if (d2 >= 90) t11 += p2;
            if (d2+1 <= -90) t10 += p3; else if (d2+1 >= 90) t11 += p3;
        }
        // PV (fp16): 4 k16-chunks
        #pragma unroll
        for (int j = 0; j < 4; j++) {
            uint32_t aP[4];
            aP[0] = pack_h2(accS[2*j][0],   accS[2*j][1]);
            aP[1] = pack_h2(accS[2*j][2],   accS[2*j][3]);
            aP[2] = pack_h2(accS[2*j+1][0], accS[2*j+1][1]);
            aP[3] = pack_h2(accS[2*j+1][2], accS[2*j+1][3]);
            #pragma unroll
            for (int nd = 0; nd < 8; nd++) {
                int n = nd * 8 + gidq;
                uint32_t bV[2];
                bV[0] = *(const uint32_t*)&Vtp[n*136 + 16*j + 2*tig];
                bV[1] = *(const uint32_t*)&Vtp[n*136 + 16*j + 2*tig + 8];
                mma_f16(accO[nd], aP, bV);
            }
        }
        __syncthreads();
    }
    #pragma unroll
    for (int o = 1; o <= 2; o <<= 1) {
        l0 += __shfl_xor_sync(0xffffffffu, l0, o);
        l1 += __shfl_xor_sync(0xffffffffu, l1, o);
        t00 += __shfl_xor_sync(0xffffffffu, t00, o);
        t01 += __shfl_xor_sync(0xffffffffu, t01, o);
        t10 += __shfl_xor_sync(0xffffffffu, t10, o);
        t11 += __shfl_xor_sync(0xffffffffu, t11, o);
    }
    float inv0 = 1.f / l0, inv1 = 1.f / l1;
    if (tig == 0) {
        g_ML[bhSs + r0] = make_float2(m0, inv0);
        g_ML[bhSs + r1] = make_float2(m1, inv1);
        BS0[0] = t00 * inv0; BS0[180] = t01 * inv0;
        BS1[0] = t10 * inv1; BS1[180] = t11 * inv1;
    }
    float* X0 = g_X + ((size_t)(b*Ss + r0)) * HID + h * Dd;
    float* X1 = g_X + ((size_t)(b*Ss + r1)) * HID + h * Dd;
    #pragma unroll
    for (int nd = 0; nd < 8; nd++) {
        int d = nd * 8 + 2 * tig;
        *(float2*)(X0 + d) = make_float2(accO[nd][0] * inv0, accO[nd][1] * inv0);
        *(float2*)(X1 + d) = make_float2(accO[nd][2] * inv1, accO[nd][3] * inv1);
    }
}

// ================= BS band normalize =================
__global__ __launch_bounds__(192) void bs_finalize()
{
    int q = blockIdx.x, bh = blockIdx.y, r = threadIdx.x;
    float* out = g_BS + ((size_t)bh * Ss + q) * RP;
    if (r >= 1 && r <= 179) {
        int k = q + r - 90;
        if (k < 0 || k >= Ss) out[r] = 0.f;
        else {
            float2 ml = g_ML[(size_t)bh * Ss + q];
            out[r] = __expf(out[r] - ml.x) * ml.y;
        }
    }
}

// ================= g_X += BS @ rel_v_emb =================
__global__ __launch_bounds__(256) void rx_add_kernel(const float* __restrict__ rv)
{
    extern __shared__ float sm[];
    float (*BSs)[193] = (float(*)[193])sm;
    float (*rvs)[64]  = (float(*)[64])(sm + 64*193);
    int bh = blockIdx.y, q0 = blockIdx.x * 64;
    int tid = threadIdx.x, tx = tid & 15, ty = tid >> 4;
    const float* BSb = g_BS + ((size_t)bh * Ss + q0) * RP;
    for (int idx = tid; idx < 64*RP; idx += 256) {
        int q = idx / RP, r = idx % RP;
        BSs[q][r] = BSb[idx];
    }
    for (int idx = tid; idx < RR*64; idx += 256) {
        int r = idx >> 6, d = idx & 63;
        rvs[r][d] = rv[idx];
    }
    __syncthreads();
    float acc[4][4];
    #pragma unroll
    for (int i = 0; i < 4; i++)
        #pragma unroll
        for (int j = 0; j < 4; j++) acc[i][j] = 0.f;
    for (int r = 0; r < RR; r++) {
        float af[4], bf[4];
        #pragma unroll
        for (int i = 0; i < 4; i++) af[i] = BSs[ty + 16*i][r];
        #pragma unroll
        for (int j = 0; j < 4; j++) bf[j] = rvs[r][tx + 16*j];
        #pragma unroll
        for (int i = 0; i < 4; i++)
            #pragma unroll
            for (int j = 0; j < 4; j++)
                acc[i][j] += af[i] * bf[j];
    }
    int b = bh >> 4, h = bh & 15;
    #pragma unroll
    for (int i = 0; i < 4; i++) {
        int q = q0 + ty + 16*i;
        #pragma unroll
        for (int j = 0; j < 4; j++) {
            int d = tx + 16*j;
            g_X[((size_t)(b*Ss + q)) * HID + h*Dd + d] += acc[i][j];
        }
    }
}

extern "C" void kernel_launch(void* const* d_in, const int* in_sizes, int n_in,
                              void* d_out, int out_size)
{
    const float* query = (const float*)d_in[0];
    const float* key   = (const float*)d_in[1];
    const float* value = (const float*)d_in[2];
    const int*   mask  = (const int*)  d_in[3];
    const float* abse  = (const float*)d_in[4];
    const float* Wq    = (const float*)d_in[5];
    const float* bq    = (const float*)d_in[6];
    const float* Wk    = (const float*)d_in[7];
    const float* bk    = (const float*)d_in[8];
    const float* Wv    = (const float*)d_in[9];
    const float* bv    = (const float*)d_in[10];
    const float* Wo    = (const float*)d_in[11];
    const float* bo    = (const float*)d_in[12];
    const float* rk    = (const float*)d_in[13];
    const float* rv    = (const float*)d_in[14];
    float* out = (float*)d_out;

    const int smem_g  = 4 * 128 * 36 * 4;      // 73728
    const int smem_fl = 2 * FL_ST;             // 192512
    const int smem_rx = (64*193 + RR*64) * 4;
    cudaFuncSetAttribute(sgemm_bias_tc, cudaFuncAttributeMaxDynamicSharedMemorySize, smem_g);
    cudaFuncSetAttribute(flash_tc,      cudaFuncAttributeMaxDynamicSharedMemorySize, smem_fl);
    cudaFuncSetAttribute(rx_add_kernel, cudaFuncAttributeMaxDynamicSharedMemorySize, smem_rx);

    dim3 gProj(HID/128, (Bb*Ss)/128);
    sgemm_bias_tc<<<gProj, 256, smem_g>>>(query, Wq, bq, nullptr, 0, 1);
    sgemm_bias_tc<<<gProj, 256, smem_g>>>(key,   Wk, bk, nullptr, 0, 2);
    sgemm_bias_tc<<<gProj, 256, smem_g>>>(value, Wv, bv, nullptr, 0, 3);

    rel_scores_tc<<<dim3(Ss/128, BH), 256>>>(rk);
    flash_tc<<<dim3(Ss/128, BH), 256, smem_fl>>>(abse, mask);
    bs_finalize<<<dim3(Ss, BH), 192>>>();
    rx_add_kernel<<<dim3(Ss/64, BH), 256, smem_rx>>>(rv);

    sgemm_bias_tc<<<gProj, 256, smem_g>>>(nullptr, Wo, bo, out, 1, 0);
}

// round 6
// speedup vs baseline: 1.7684x; 1.1731x over previous
#include <cuda_runtime.h>
#include <cuda_fp16.h>
#include <math.h>
#include <stdint.h>

#define Bb   4
#define Ss   1024
#define Hh   16
#define Dd   64
#define HID  1024
#define BH   (Bb*Hh)
#define RR   181
#define RP   192
#define TK   32

__device__ float  g_Q [(size_t)BH * Ss * Dd];
__device__ __half g_Kh[(size_t)BH * Ss * Dd];   // [bh][s][d]
__device__ __half g_Vh[(size_t)BH * Dd * Ss];   // [bh][d][s] (transposed)
__device__ float  g_RS[(size_t)BH * Ss * RP];
__device__ float  g_BS[(size_t)BH * Ss * RP];
__device__ float  g_X [(size_t)Bb * Ss * HID];
__device__ float2 g_ML[(size_t)BH * Ss];

__device__ __forceinline__ uint32_t cvt_tf32(float x) {
    uint32_t r; asm("cvt.rna.tf32.f32 %0, %1;" : "=r"(r) : "f"(x)); return r;
}
__device__ __forceinline__ void mma_tf32(float c[4], const uint32_t a[4], const uint32_t b[2]) {
    asm volatile(
        "mma.sync.aligned.m16n8k8.row.col.f32.tf32.tf32.f32 "
        "{%0,%1,%2,%3}, {%4,%5,%6,%7}, {%8,%9}, {%0,%1,%2,%3};"
        : "+f"(c[0]), "+f"(c[1]), "+f"(c[2]), "+f"(c[3])
        : "r"(a[0]), "r"(a[1]), "r"(a[2]), "r"(a[3]), "r"(b[0]), "r"(b[1]));
}
__device__ __forceinline__ void mma_f16(float c[4], const uint32_t a[4], const uint32_t b[2]) {
    asm volatile(
        "mma.sync.aligned.m16n8k16.row.col.f32.f16.f16.f32 "
        "{%0,%1,%2,%3}, {%4,%5,%6,%7}, {%8,%9}, {%0,%1,%2,%3};"
        : "+f"(c[0]), "+f"(c[1]), "+f"(c[2]), "+f"(c[3])
        : "r"(a[0]), "r"(a[1]), "r"(a[2]), "r"(a[3]), "r"(b[0]), "r"(b[1]));
}
__device__ __forceinline__ uint32_t pack_h2(float lo, float hi) {
    uint32_t r; asm("cvt.rn.f16x2.f32 %0, %1, %2;" : "=r"(r) : "f"(hi), "f"(lo)); return r;
}
__device__ __forceinline__ void cpa16(void* s, const void* g) {
    uint32_t sa = (uint32_t)__cvta_generic_to_shared(s);
    asm volatile("cp.async.cg.shared.global [%0], [%1], 16;" :: "r"(sa), "l"(g));
}
__device__ __forceinline__ void cp_commit() { asm volatile("cp.async.commit_group;"); }
__device__ __forceinline__ void cp_wait1()  { asm volatile("cp.async.wait_group 1;"); }

// ================= fp16 GEMM, cp.async 2-stage: C = A @ W^T + bias =================
// out_mode: 0 Cout f32 [M,N]; 1 g_Q f32 [bh][s][d]; 2 g_Kh half [bh][s][d]; 3 g_Vh half [bh][d][s]
__device__ __forceinline__ void gemm_load(float* As, float* Bs,
    const float* A, const float* W, int bm, int bn, int k0, int tid)
{
    #pragma unroll
    for (int i = 0; i < 4; i++) {
        int idx = tid + 256 * i;
        int row = idx >> 3, c = (idx & 7) * 4;
        cpa16(&As[row*36 + c], A + (size_t)(bm + row) * HID + k0 + c);
        cpa16(&Bs[row*36 + c], W + (size_t)(bn + row) * HID + k0 + c);
    }
}

__global__ __launch_bounds__(256) void sgemm_bias_tc(
    const float* __restrict__ Ain, const float* __restrict__ W,
    const float* __restrict__ bias, float* __restrict__ Cout,
    int a_sel, int out_mode)
{
    extern __shared__ float smg[];
    float* As[2] = { smg, smg + 128*36 };
    float* Bs[2] = { smg + 2*128*36, smg + 3*128*36 };
    const float* A = (a_sel == 1) ? g_X : Ain;
    const int tid = threadIdx.x, lane = tid & 31, wid = tid >> 5;
    const int gidq = lane >> 2, tig = lane & 3;
    const int warp_m = (wid & 1) * 64, warp_n = (wid >> 1) * 32;
    const int bm = blockIdx.y * 128, bn = blockIdx.x * 128;

    float acc[4][4][4];
    #pragma unroll
    for (int i = 0; i < 4; i++)
        #pragma unroll
        for (int j = 0; j < 4; j++)
            #pragma unroll
            for (int r = 0; r < 4; r++) acc[i][j][r] = 0.f;

    gemm_load(As[0], Bs[0], A, W, bm, bn, 0, tid);
    cp_commit();

    for (int it = 0; it < 32; it++) {
        int st = it & 1;
        if (it < 31) gemm_load(As[st^1], Bs[st^1], A, W, bm, bn, (it+1)*32, tid);
        cp_commit();
        cp_wait1();
        __syncthreads();
        const float* Ap = As[st];
        const float* Bp = Bs[st];
        #pragma unroll
        for (int kk = 0; kk < 32; kk += 16) {
            uint32_t af[4][4], bf[4][2];
            #pragma unroll
            for (int ma = 0; ma < 4; ma++) {
                int m = warp_m + 16 * ma + gidq;
                float2 v0 = *(const float2*)&Ap[m*36 + kk + 2*tig];
                float2 v1 = *(const float2*)&Ap[(m+8)*36 + kk + 2*tig];
                float2 v2 = *(const float2*)&Ap[m*36 + kk + 2*tig + 8];
                float2 v3 = *(const float2*)&Ap[(m+8)*36 + kk + 2*tig + 8];
                af[ma][0] = pack_h2(v0.x, v0.y);
                af[ma][1] = pack_h2(v1.x, v1.y);
                af[ma][2] = pack_h2(v2.x, v2.y);
                af[ma][3] = pack_h2(v3.x, v3.y);
            }
            #pragma unroll
            for (int nb = 0; nb < 4; nb++) {
                int n = warp_n + 8 * nb + gidq;
                float2 w0 = *(const float2*)&Bp[n*36 + kk + 2*tig];
                float2 w1 = *(const float2*)&Bp[n*36 + kk + 2*tig + 8];
                bf[nb][0] = pack_h2(w0.x, w0.y);
                bf[nb][1] = pack_h2(w1.x, w1.y);
            }
            #pragma unroll
            for (int ma = 0; ma < 4; ma++)
                #pragma unroll
                for (int nb = 0; nb < 4; nb++)
                    mma_f16(acc[ma][nb], af[ma], bf[nb]);
        }
        __syncthreads();
    }

    #pragma unroll
    for (int ma = 0; ma < 4; ma++) {
        #pragma unroll
        for (int nb = 0; nb < 4; nb++) {
            int n0 = bn + warp_n + 8 * nb + 2 * tig;
            float bx = bias[n0], by = bias[n0 + 1];
            #pragma unroll
            for (int half = 0; half < 2; half++) {
                int m = bm + warp_m + 16 * ma + gidq + 8 * half;
                float vx = acc[ma][nb][2*half+0] + bx;
                float vy = acc[ma][nb][2*half+1] + by;
                if (out_mode == 0) {
                    *(float2*)(Cout + (size_t)m * HID + n0) = make_float2(vx, vy);
                } else {
                    int b = m >> 10, s = m & 1023, h = n0 >> 6, d = n0 & 63;
                    size_t bh = (size_t)(b * Hh + h);
                    if (out_mode == 1) {
                        *(float2*)(g_Q + (bh * Ss + s) * Dd + d) = make_float2(vx, vy);
                    } else if (out_mode == 2) {
                        *(__half2*)(g_Kh + (bh * Ss + s) * Dd + d) = __floats2half2_rn(vx, vy);
                    } else {
                        g_Vh[(bh * Dd + d) * Ss + s]     = __float2half(vx);
                        g_Vh[(bh * Dd + d + 1) * Ss + s] = __float2half(vy);
                    }
                }
            }
        }
    }
}

// ================= RS = Q @ rel_k_emb^T (tf32) =================
__global__ __launch_bounds__(256) void rel_scores_tc(const float* __restrict__ rk)
{
    __shared__ float As[32][136];
    __shared__ float Bs[32][200];
    int bh = blockIdx.y, q0 = blockIdx.x * 128;
    const int tid = threadIdx.x, lane = tid & 31, wid = tid >> 5;
    const int gidq = lane >> 2, tig = lane & 3;
    const int warp_m = (wid & 1) * 64, warp_n = (wid >> 1) * 48;
    const int srow = tid & 31, scol = (tid >> 5) * 4;
    const float* Qb = g_Q + ((size_t)bh * Ss + q0) * Dd;
    float acc[4][6][4];
    #pragma unroll
    for (int i = 0; i < 4; i++)
        #pragma unroll
        for (int j = 0; j < 6; j++)
            #pragma unroll
            for (int r = 0; r < 4; r++) acc[i][j][r] = 0.f;
    for (int k0 = 0; k0 < 64; k0 += 32) {
        #pragma unroll
        for (int i = 0; i < 4; i++) {
            int ml = srow + 32 * i;
            float4 va = *(const float4*)(Qb + (size_t)ml * Dd + k0 + scol);
            As[scol+0][ml]=__uint_as_float(cvt_tf32(va.x)); As[scol+1][ml]=__uint_as_float(cvt_tf32(va.y));
            As[scol+2][ml]=__uint_as_float(cvt_tf32(va.z)); As[scol+3][ml]=__uint_as_float(cvt_tf32(va.w));
        }
        #pragma unroll
        for (int i = 0; i < 6; i++) {
            int rl = srow + 32 * i;
            float4 vb = (rl < RR) ? *(const float4*)(rk + (size_t)rl * Dd + k0 + scol)
                                  : make_float4(0.f,0.f,0.f,0.f);
            Bs[scol+0][rl]=__uint_as_float(cvt_tf32(vb.x)); Bs[scol+1][rl]=__uint_as_float(cvt_tf32(vb.y));
            Bs[scol+2][rl]=__uint_as_float(cvt_tf32(vb.z)); Bs[scol+3][rl]=__uint_as_float(cvt_tf32(vb.w));
        }
        __syncthreads();
        #pragma unroll
        for (int kk = 0; kk < 32; kk += 8) {
            uint32_t af[4][4], bf[6][2];
            #pragma unroll
            for (int ma = 0; ma < 4; ma++) {
                int m = warp_m + 16 * ma + gidq;
                af[ma][0]=__float_as_uint(As[kk+tig][m]);   af[ma][1]=__float_as_uint(As[kk+tig][m+8]);
                af[ma][2]=__float_as_uint(As[kk+tig+4][m]); af[ma][3]=__float_as_uint(As[kk+tig+4][m+8]);
            }
            #pragma unroll
            for (int nb = 0; nb < 6; nb++) {
                int n = warp_n + 8 * nb + gidq;
                bf[nb][0]=__float_as_uint(Bs[kk+tig][n]); bf[nb][1]=__float_as_uint(Bs[kk+tig+4][n]);
            }
            #pragma unroll
            for (int ma = 0; ma < 4; ma++)
                #pragma unroll
                for (int nb = 0; nb < 6; nb++)
                    mma_tf32(acc[ma][nb], af[ma], bf[nb]);
        }
        __syncthreads();
    }
    float* out = g_RS + ((size_t)bh * Ss + q0) * RP;
    #pragma unroll
    for (int ma = 0; ma < 4; ma++) {
        int qm = warp_m + 16 * ma + gidq;
        #pragma unroll
        for (int nb = 0; nb < 6; nb++) {
            int r0 = warp_n + 8 * nb + 2 * tig;
            #pragma unroll
            for (int half = 0; half < 2; half++) {
                int q = qm + 8 * half;
                if (r0 < RR)     out[(size_t)q * RP + r0]     = acc[ma][nb][2*half+0];
                if (r0 + 1 < RR) out[(size_t)q * RP + r0 + 1] = acc[ma][nb][2*half+1];
            }
        }
    }
}

// ================= Fused flash attention (fp16 mma, cp.async 2-stage, TK=32) =================
// stage layout (bytes): Kt half[32][72] @0 (4608) | Vt half[64][40] @4608 (5120)
//                       ab float[128][36] @9728 (18432) | mk int[128][36] @28160 (18432)
#define FL_ST 46592

__device__ __forceinline__ void flash_load_tile(char* base, int kt, int tid,
    const __half* Kg, const __half* Vg, const float* abrow, const int* mkrow)
{
    __half* Ktp = (__half*)base;
    __half* Vtp = (__half*)(base + 4608);
    float*  abp = (float*)(base + 9728);
    int*    mkp = (int*)(base + 28160);
    int k0 = kt * TK;
    {
        int r = tid >> 3, c = (tid & 7) * 8;          // 32 rows x 64 halves
        cpa16(&Ktp[r*72 + c], Kg + (size_t)(k0 + r) * Dd + c);
    }
    {
        int r = tid >> 2, c = (tid & 3) * 8;          // 64 rows x 32 halves
        cpa16(&Vtp[r*40 + c], Vg + (size_t)r * Ss + k0 + c);
    }
    #pragma unroll
    for (int i = 0; i < 4; i++) {
        int idx = tid + 256 * i;
        int r = idx >> 3, c = (idx & 7) * 4;          // 128 rows x 32 floats
        cpa16(&abp[r*36 + c], abrow + (size_t)r * Ss + k0 + c);
        cpa16(&mkp[r*36 + c], mkrow + (size_t)r * Ss + k0 + c);
    }
}

__global__ __launch_bounds__(256, 2) void flash_tc(
    const float* __restrict__ abse, const int* __restrict__ mask)
{
    extern __shared__ char smb[];
    const int bh = blockIdx.y, q0 = blockIdx.x * 128;
    const int b = bh >> 4, h = bh & 15;
    const int tid = threadIdx.x, lane = tid & 31, wid = tid >> 5;
    const int gidq = lane >> 2, tig = lane & 3;
    const int ql0 = wid * 16 + gidq, ql1 = ql0 + 8;
    const int r0 = q0 + ql0, r1 = q0 + ql1;
    const size_t bhSs = (size_t)bh * Ss;
    const __half* Kg = g_Kh + bhSs * Dd;
    const __half* Vg = g_Vh + (size_t)bh * Dd * Ss;
    const float* abrow = abse + ((size_t)h * Ss + q0) * Ss;
    const int*   mkrow = mask + ((size_t)b * Ss + q0) * Ss;

    uint32_t qh[4][4];
    {
        const float* Q0 = g_Q + (bhSs + r0) * Dd;
        const float* Q1 = g_Q + (bhSs + r1) * Dd;
        #pragma unroll
        for (int c = 0; c < 4; c++) {
            float2 a0 = *(const float2*)(Q0 + 16*c + 2*tig);
            float2 a1 = *(const float2*)(Q1 + 16*c + 2*tig);
            float2 a2 = *(const float2*)(Q0 + 16*c + 2*tig + 8);
            float2 a3 = *(const float2*)(Q1 + 16*c + 2*tig + 8);
            qh[c][0] = pack_h2(a0.x, a0.y); qh[c][1] = pack_h2(a1.x, a1.y);
            qh[c][2] = pack_h2(a2.x, a2.y); qh[c][3] = pack_h2(a3.x, a3.y);
        }
    }
    const float* RS0 = g_RS + (bhSs + r0) * RP;
    const float* RS1 = g_RS + (bhSs + r1) * RP;
    const float rs_lo0 = RS0[0], rs_hi0 = RS0[180];
    const float rs_lo1 = RS1[0], rs_hi1 = RS1[180];
    float* BS0 = g_BS + (bhSs + r0) * RP;
    float* BS1 = g_BS + (bhSs + r1) * RP;

    flash_load_tile(smb, 0, tid, Kg, Vg, abrow, mkrow);
    cp_commit();

    float m0 = -1e30f, m1 = -1e30f, l0 = 0.f, l1 = 0.f;
    float t00 = 0.f, t01 = 0.f, t10 = 0.f, t11 = 0.f;
    float accO[8][4];
    #pragma unroll
    for (int i = 0; i < 8; i++)
        #pragma unroll
        for (int j = 0; j < 4; j++) accO[i][j] = 0.f;

    for (int kt = 0; kt < 32; kt++) {
        const int st = kt & 1;
        if (kt < 31) flash_load_tile(smb + (st^1)*FL_ST, kt+1, tid, Kg, Vg, abrow, mkrow);
        cp_commit();
        cp_wait1();
        __syncthreads();
        char* base = smb + st * FL_ST;
        const __half* Ktp = (const __half*)base;
        const __half* Vtp = (const __half*)(base + 4608);
        const float*  abp = (const float*)(base + 9728);
        const int*    mkp = (const int*)(base + 28160);
        const int k0 = kt * TK;

        // S = Q K^T (16 x 32 per warp)
        float accS[4][4];
        #pragma unroll
        for (int nb = 0; nb < 4; nb++)
            #pragma unroll
            for (int r = 0; r < 4; r++) accS[nb][r] = 0.f;
        #pragma unroll
        for (int c = 0; c < 4; c++) {
            #pragma unroll
            for (int nb = 0; nb < 4; nb++) {
                int n = nb * 8 + gidq;
                uint32_t bf[2];
                bf[0] = *(const uint32_t*)&Ktp[n*72 + 16*c + 2*tig];
                bf[1] = *(const uint32_t*)&Ktp[n*72 + 16*c + 2*tig + 8];
                mma_f16(accS[nb], qh[c], bf);
            }
        }
        // energy epilogue + band stores
        float mt0 = -1e30f, mt1 = -1e30f;
        #pragma unroll
        for (int nb = 0; nb < 4; nb++) {
            int kcl = nb * 8 + 2 * tig;
            int kc = k0 + kcl;
            float2 av = *(const float2*)&abp[ql0*36 + kcl];
            int2   mv = *(const int2*)&mkp[ql0*36 + kcl];
            int d0 = kc - r0;
            float rv0 = (d0 <= -90) ? rs_lo0 : (d0 >= 90) ? rs_hi0 : RS0[d0 + 90];
            float rv1 = (d0+1 <= -90) ? rs_lo0 : (d0+1 >= 90) ? rs_hi0 : RS0[d0 + 91];
            float e0 = (accS[nb][0] + av.x + rv0) * 0.125f; if (!mv.x) e0 = -1e10f;
            float e1 = (accS[nb][1] + av.y + rv1) * 0.125f; if (!mv.y) e1 = -1e10f;
            if (d0 > -90 && d0 < 90)     BS0[d0 + 90] = e0;
            if (d0+1 > -90 && d0+1 < 90) BS0[d0 + 91] = e1;
            accS[nb][0] = e0; accS[nb][1] = e1;
            mt0 = fmaxf(mt0, fmaxf(e0, e1));
            float2 aw = *(const float2*)&abp[ql1*36 + kcl];
            int2   mw = *(const int2*)&mkp[ql1*36 + kcl];
            int d2 = kc - r1;
            float rv2 = (d2 <= -90) ? rs_lo1 : (d2 >= 90) ? rs_hi1 : RS1[d2 + 90];
            float rv3 = (d2+1 <= -90) ? rs_lo1 : (d2+1 >= 90) ? rs_hi1 : RS1[d2 + 91];
            float e2 = (accS[nb][2] + aw.x + rv2) * 0.125f; if (!mw.x) e2 = -1e10f;
            float e3 = (accS[nb][3] + aw.y + rv3) * 0.125f; if (!mw.y) e3 = -1e10f;
            if (d2 > -90 && d2 < 90)     BS1[d2 + 90] = e2;
            if (d2+1 > -90 && d2+1 < 90) BS1[d2 + 91] = e3;
            accS[nb][2] = e2; accS[nb][3] = e3;
            mt1 = fmaxf(mt1, fmaxf(e2, e3));
        }
        mt0 = fmaxf(mt0, __shfl_xor_sync(0xffffffffu, mt0, 1));
        mt0 = fmaxf(mt0, __shfl_xor_sync(0xffffffffu, mt0, 2));
        mt1 = fmaxf(mt1, __shfl_xor_sync(0xffffffffu, mt1, 1));
        mt1 = fmaxf(mt1, __shfl_xor_sync(0xffffffffu, mt1, 2));
        float mn0 = fmaxf(m0, mt0), mn1 = fmaxf(m1, mt1);
        float sc0 = __expf(m0 - mn0), sc1 = __expf(m1 - mn1);
        m0 = mn0; m1 = mn1;
        l0 *= sc0; l1 *= sc1; t00 *= sc0; t01 *= sc0; t10 *= sc1; t11 *= sc1;
        #pragma unroll
        for (int nd = 0; nd < 8; nd++) {
            accO[nd][0] *= sc0; accO[nd][1] *= sc0;
            accO[nd][2] *= sc1; accO[nd][3] *= sc1;
        }
        #pragma unroll
        for (int nb = 0; nb < 4; nb++) {
            int kc = k0 + nb * 8 + 2 * tig;
            float p0 = __expf(accS[nb][0] - m0);
            float p1 = __expf(accS[nb][1] - m0);
            float p2 = __expf(accS[nb][2] - m1);
            float p3 = __expf(accS[nb][3] - m1);
            accS[nb][0] = p0; accS[nb][1] = p1; accS[nb][2] = p2; accS[nb][3] = p3;
            l0 += p0 + p1; l1 += p2 + p3;
            int d0 = kc - r0, d2 = kc - r1;
            if (d0 <= -90) t00 += p0; else if (d0 >= 90) t01 += p0;
            if (d0+1 <= -90) t00 += p1; else if (d0+1 >= 90) t01 += p1;
            if (d2 <= -90) t10 += p2; else if (d2 >= 90) t11 += p2;
            if (d2+1 <= -90) t10 += p3; else if (d2+1 >= 90) t11 += p3;
        }
        // PV (fp16): 2 k16-chunks
        #pragma unroll
        for (int j = 0; j < 2; j++) {
            uint32_t aP[4];
            aP[0] = pack_h2(accS[2*j][0],   accS[2*j][1]);
            aP[1] = pack_h2(accS[2*j][2],   accS[2*j][3]);
            aP[2] = pack_h2(accS[2*j+1][0], accS[2*j+1][1]);
            aP[3] = pack_h2(accS[2*j+1][2], accS[2*j+1][3]);
            #pragma unroll
            for (int nd = 0; nd < 8; nd++) {
                int n = nd * 8 + gidq;
                uint32_t bV[2];
                bV[0] = *(const uint32_t*)&Vtp[n*40 + 16*j + 2*tig];
                bV[1] = *(const uint32_t*)&Vtp[n*40 + 16*j + 2*tig + 8];
                mma_f16(accO[nd], aP, bV);
            }
        }
        __syncthreads();
    }
    #pragma unroll
    for (int o = 1; o <= 2; o <<= 1) {
        l0 += __shfl_xor_sync(0xffffffffu, l0, o);
        l1 += __shfl_xor_sync(0xffffffffu, l1, o);
        t00 += __shfl_xor_sync(0xffffffffu, t00, o);
        t01 += __shfl_xor_sync(0xffffffffu, t01, o);
        t10 += __shfl_xor_sync(0xffffffffu, t10, o);
        t11 += __shfl_xor_sync(0xffffffffu, t11, o);
    }
    float inv0 = 1.f / l0, inv1 = 1.f / l1;
    if (tig == 0) {
        g_ML[bhSs + r0] = make_float2(m0, inv0);
        g_ML[bhSs + r1] = make_float2(m1, inv1);
        BS0[0] = t00 * inv0; BS0[180] = t01 * inv0;
        BS1[0] = t10 * inv1; BS1[180] = t11 * inv1;
    }
    float* X0 = g_X + ((size_t)(b*Ss + r0)) * HID + h * Dd;
    float* X1 = g_X + ((size_t)(b*Ss + r1)) * HID + h * Dd;
    #pragma unroll
    for (int nd = 0; nd < 8; nd++) {
        int d = nd * 8 + 2 * tig;
        *(float2*)(X0 + d) = make_float2(accO[nd][0] * inv0, accO[nd][1] * inv0);
        *(float2*)(X1 + d) = make_float2(accO[nd][2] * inv1, accO[nd][3] * inv1);
    }
}

// ================= BS band normalize =================
__global__ __launch_bounds__(192) void bs_finalize()
{
    int q = blockIdx.x, bh = blockIdx.y, r = threadIdx.x;
    float* out = g_BS + ((size_t)bh * Ss + q) * RP;
    if (r >= 1 && r <= 179) {
        int k = q + r - 90;
        if (k < 0 || k >= Ss) out[r] = 0.f;
        else {
            float2 ml = g_ML[(size_t)bh * Ss + q];
            out[r] = __expf(out[r] - ml.x) * ml.y;
        }
    }
}

// ================= g_X += BS @ rel_v_emb =================
__global__ __launch_bounds__(256) void rx_add_kernel(const float* __restrict__ rv)
{
    extern __shared__ float sm[];
    float (*BSs)[193] = (float(*)[193])sm;
    float (*rvs)[64]  = (float(*)[64])(sm + 64*193);
    int bh = blockIdx.y, q0 = blockIdx.x * 64;
    int tid = threadIdx.x, tx = tid & 15, ty = tid >> 4;
    const float* BSb = g_BS + ((size_t)bh * Ss + q0) * RP;
    for (int idx = tid; idx < 64*RP; idx += 256) {
        int q = idx / RP, r = idx % RP;
        BSs[q][r] = BSb[idx];
    }
    for (int idx = tid; idx < RR*64; idx += 256) {
        int r = idx >> 6, d = idx & 63;
        rvs[r][d] = rv[idx];
    }
    __syncthreads();
    float acc[4][4];
    #pragma unroll
    for (int i = 0; i < 4; i++)
        #pragma unroll
        for (int j = 0; j < 4; j++) acc[i][j] = 0.f;
    for (int r = 0; r < RR; r++) {
        float af[4], bf[4];
        #pragma unroll
        for (int i = 0; i < 4; i++) af[i] = BSs[ty + 16*i][r];
        #pragma unroll
        for (int j = 0; j < 4; j++) bf[j] = rvs[r][tx + 16*j];
        #pragma unroll
        for (int i = 0; i < 4; i++)
            #pragma unroll
            for (int j = 0; j < 4; j++)
                acc[i][j] += af[i] * bf[j];
    }
    int b = bh >> 4, h = bh & 15;
    #pragma unroll
    for (int i = 0; i < 4; i++) {
        int q = q0 + ty + 16*i;
        #pragma unroll
        for (int j = 0; j < 4; j++) {
            int d = tx + 16*j;
            g_X[((size_t)(b*Ss + q)) * HID + h*Dd + d] += acc[i][j];
        }
    }
}

extern "C" void kernel_launch(void* const* d_in, const int* in_sizes, int n_in,
                              void* d_out, int out_size)
{
    const float* query = (const float*)d_in[0];
    const float* key   = (const float*)d_in[1];
    const float* value = (const float*)d_in[2];
    const int*   mask  = (const int*)  d_in[3];
    const float* abse  = (const float*)d_in[4];
    const float* Wq    = (const float*)d_in[5];
    const float* bq    = (const float*)d_in[6];
    const float* Wk    = (const float*)d_in[7];
    const float* bk    = (const float*)d_in[8];
    const float* Wv    = (const float*)d_in[9];
    const float* bv    = (const float*)d_in[10];
    const float* Wo    = (const float*)d_in[11];
    const float* bo    = (const float*)d_in[12];
    const float* rk    = (const float*)d_in[13];
    const float* rv    = (const float*)d_in[14];
    float* out = (float*)d_out;

    const int smem_g  = 4 * 128 * 36 * 4;      // 73728
    const int smem_fl = 2 * FL_ST;             // 93184
    const int smem_rx = (64*193 + RR*64) * 4;
    cudaFuncSetAttribute(sgemm_bias_tc, cudaFuncAttributeMaxDynamicSharedMemorySize, smem_g);
    cudaFuncSetAttribute(flash_tc,      cudaFuncAttributeMaxDynamicSharedMemorySize, smem_fl);
    cudaFuncSetAttribute(rx_add_kernel, cudaFuncAttributeMaxDynamicSharedMemorySize, smem_rx);

    dim3 gProj(HID/128, (Bb*Ss)/128);
    sgemm_bias_tc<<<gProj, 256, smem_g>>>(query, Wq, bq, nullptr, 0, 1);
    sgemm_bias_tc<<<gProj, 256, smem_g>>>(key,   Wk, bk, nullptr, 0, 2);
    sgemm_bias_tc<<<gProj, 256, smem_g>>>(value, Wv, bv, nullptr, 0, 3);

    rel_scores_tc<<<dim3(Ss/128, BH), 256>>>(rk);
    flash_tc<<<dim3(Ss/128, BH), 256, smem_fl>>>(abse, mask);
    bs_finalize<<<dim3(Ss, BH), 192>>>();
    rx_add_kernel<<<dim3(Ss/64, BH), 256, smem_rx>>>(rv);

    sgemm_bias_tc<<<gProj, 256, smem_g>>>(nullptr, Wo, bo, out, 1, 0);
}